// round 5
// baseline (speedup 1.0000x reference)
#include <cuda_runtime.h>

// ---------------- problem constants ----------------
#define B_   2
#define L_   2048
#define D_   512
#define P_   32
#define M_   1024
#define H_   8
#define HD_  64
#define WIN_ 256
#define S_   (P_ + L_)     // 2080
#define R_   (B_ * S_)     // 4160
#define EPS_ 1e-5f

// m16n8k8 tf32 MMA, D (+)= A*B, accumulate in place
#define MMA_TF32(d, a0, a1, a2, a3, b0, b1) \
    asm("mma.sync.aligned.m16n8k8.row.col.f32.tf32.tf32.f32 " \
        "{%0,%1,%2,%3}, {%4,%5,%6,%7}, {%8,%9}, {%0,%1,%2,%3};" \
        : "+f"((d)[0]), "+f"((d)[1]), "+f"((d)[2]), "+f"((d)[3]) \
        : "r"(a0), "r"(a1), "r"(a2), "r"(a3), "r"(b0), "r"(b1))

// ---------------- scratch (device globals, no allocation) ----------------
__device__ float g_combined[R_ * D_];
__device__ float g_k[R_ * D_];
__device__ float g_v[R_ * D_];
__device__ float g_q[R_ * D_];
__device__ float g_w[R_ * M_];          // w_write
__device__ float g_w2[R_ * M_];         // w_read
__device__ float g_state[B_ * M_ * D_];
__device__ float g_memout[R_ * D_];
__device__ float g_h[R_ * D_];
__device__ float g_qh[R_ * D_];
__device__ float g_kh[R_ * D_];
__device__ float g_vh[R_ * D_];
__device__ float g_aout[R_ * D_];
__device__ float g_ao2[R_ * D_];
__device__ float g_h2[R_ * D_];

// ---------------- concat: combined = [persistent ; x] ----------------
__global__ void concat_kernel(const float* __restrict__ x,
                              const float* __restrict__ pm,
                              float* __restrict__ c) {
    long i = (long)blockIdx.x * 256 + threadIdx.x;
    if (i >= (long)R_ * D_) return;
    int d = (int)(i % D_);
    long sd = i / D_;
    int s = (int)(sd % S_);
    int b = (int)(sd / S_);
    c[i] = (s < P_) ? pm[s * D_ + d]
                    : x[((long)b * L_ + (s - P_)) * D_ + d];
}

// ---------------- 3xTF32 tensor-core GEMM: 128x128x16, 256 threads ------
// C[M x N] = A @ B (+ optional bias over N), fp32-accurate via hi/lo split:
//   D += Ahi*Bhi + Ahi*Blo + Alo*Bhi   (hi = cvt.rna.tf32, lo = re-rounded residual)
// AMODE=0: A row-major M x K.  AMODE=1: A stored K x M (use A^T, ld M).
// BMODE=0: B row-major K x N.  BMODE=1: B stored N x K (use B^T, ld K).
// Requirements: K % 16 == 0, N % 128 == 0; M guarded (valid M multiple of 8).
// smem k-interleave: element (m,k) at ((k>>3)*128 + m)*8 + (k&3)*2 + ((k>>2)&1)
// so fragment pairs {k, k+4} are adjacent -> one LDS.64, lane stride 8B (no conflicts).
template<int AMODE, int BMODE>
__device__ __forceinline__ void gemm_core_tf32(
    const float* __restrict__ A, const float* __restrict__ Bm,
    float* __restrict__ C, int M, int N, int K, const float* __restrict__ bias) {
    __shared__ __align__(16) unsigned Ah[2048], Al[2048];   // 16 KB
    __shared__ __align__(16) unsigned Bh[2048], Bl[2048];   // 16 KB
    const int tid  = threadIdx.x;
    const int lane = tid & 31;
    const int wid  = tid >> 5;
    const int wm = (wid >> 2) * 64;        // warp m-offset: 0 / 64
    const int wn = (wid & 3) * 32;         // warp n-offset: 0/32/64/96
    const int m0 = blockIdx.y * 128, n0 = blockIdx.x * 128;

    float acc[4][4][4];                    // [i m16-frag][j n8-frag][c0..c3]
#pragma unroll
    for (int i = 0; i < 4; i++)
#pragma unroll
        for (int j = 0; j < 4; j++)
#pragma unroll
            for (int c = 0; c < 4; c++) acc[i][j][c] = 0.f;

    float4 pa0, pa1, pb0, pb1;

    auto loadA = [&](int k0) {
        if (AMODE == 0) {
            int row = tid >> 1, koff = (tid & 1) << 3;
            bool ok = (m0 + row < M);
            const float* p = A + (long)(m0 + row) * K + k0 + koff;
            pa0 = ok ? *(const float4*)(p)     : make_float4(0.f, 0.f, 0.f, 0.f);
            pa1 = ok ? *(const float4*)(p + 4) : make_float4(0.f, 0.f, 0.f, 0.f);
        } else {
            int k = tid >> 4, mq = (tid & 15) << 3;
            bool ok = (m0 + mq < M);
            const float* p = A + (long)(k0 + k) * M + m0 + mq;
            pa0 = ok ? *(const float4*)(p)     : make_float4(0.f, 0.f, 0.f, 0.f);
            pa1 = ok ? *(const float4*)(p + 4) : make_float4(0.f, 0.f, 0.f, 0.f);
        }
    };
    auto loadB = [&](int k0) {
        if (BMODE == 0) {
            int k = tid >> 4, nq = (tid & 15) << 3;
            const float* p = Bm + (long)(k0 + k) * N + n0 + nq;
            pb0 = *(const float4*)(p);
            pb1 = *(const float4*)(p + 4);
        } else {
            int col = tid >> 1, koff = (tid & 1) << 3;
            const float* p = Bm + (long)(n0 + col) * K + k0 + koff;
            pb0 = *(const float4*)(p);
            pb1 = *(const float4*)(p + 4);
        }
    };

    auto cvt_store = [&](float x, int off, unsigned* __restrict__ Hi,
                         unsigned* __restrict__ Lo) {
        unsigned hb;
        asm("cvt.rna.tf32.f32 %0, %1;" : "=r"(hb) : "f"(x));
        float res = x - __uint_as_float(hb);
        unsigned lb;
        asm("cvt.rna.tf32.f32 %0, %1;" : "=r"(lb) : "f"(res));
        Hi[off] = hb; Lo[off] = lb;
    };
    // store 8 k-consecutive values (v4a = k..k+3, v4b = k+4..k+7) for one (m)
    // row base, in interleaved slot order {a.x,b.x,a.y,b.y,a.z,b.z,a.w,b.w}
    auto store_krow = [&](float4 a, float4 b, int base,
                          unsigned* Hi, unsigned* Lo) {
        cvt_store(a.x, base + 0, Hi, Lo); cvt_store(b.x, base + 1, Hi, Lo);
        cvt_store(a.y, base + 2, Hi, Lo); cvt_store(b.y, base + 3, Hi, Lo);
        cvt_store(a.z, base + 4, Hi, Lo); cvt_store(b.z, base + 5, Hi, Lo);
        cvt_store(a.w, base + 6, Hi, Lo); cvt_store(b.w, base + 7, Hi, Lo);
    };
    auto storeA = [&]() {
        if (AMODE == 0) {
            int row = tid >> 1, ko = tid & 1;
            store_krow(pa0, pa1, (ko * 128 + row) * 8, Ah, Al);
        } else {
            int k = tid >> 4, mq = (tid & 15) << 3;
            int slot = (k & 3) * 2 + ((k >> 2) & 1), ko = k >> 3;
            const float* v0 = &pa0.x; const float* v1 = &pa1.x;
#pragma unroll
            for (int ii = 0; ii < 4; ii++) {
                cvt_store(v0[ii], (ko * 128 + mq + ii) * 8 + slot, Ah, Al);
                cvt_store(v1[ii], (ko * 128 + mq + 4 + ii) * 8 + slot, Ah, Al);
            }
        }
    };
    auto storeB = [&]() {
        if (BMODE == 0) {
            int k = tid >> 4, nq = (tid & 15) << 3;
            int slot = (k & 3) * 2 + ((k >> 2) & 1), ko = k >> 3;
            const float* v0 = &pb0.x; const float* v1 = &pb1.x;
#pragma unroll
            for (int ii = 0; ii < 4; ii++) {
                cvt_store(v0[ii], (ko * 128 + nq + ii) * 8 + slot, Bh, Bl);
                cvt_store(v1[ii], (ko * 128 + nq + 4 + ii) * 8 + slot, Bh, Bl);
            }
        } else {
            int col = tid >> 1, ko = tid & 1;
            store_krow(pb0, pb1, (ko * 128 + col) * 8, Bh, Bl);
        }
    };

    const int slabs = K / 16;
    loadA(0); loadB(0);
    storeA(); storeB();
    __syncthreads();

    for (int s = 0; s < slabs; s++) {
        if (s + 1 < slabs) { loadA((s + 1) * 16); loadB((s + 1) * 16); }
#pragma unroll
        for (int ko = 0; ko < 2; ko++) {
            unsigned bh[4][2], bl[4][2];
#pragma unroll
            for (int j = 0; j < 4; j++) {
                int ob = (ko * 128 + wn + j * 8 + (lane >> 2)) * 8 + (lane & 3) * 2;
                uint2 th = *(const uint2*)&Bh[ob]; bh[j][0] = th.x; bh[j][1] = th.y;
                uint2 tl = *(const uint2*)&Bl[ob]; bl[j][0] = tl.x; bl[j][1] = tl.y;
            }
#pragma unroll
            for (int i = 0; i < 4; i++) {
                int oa = (ko * 128 + wm + i * 16 + (lane >> 2)) * 8 + (lane & 3) * 2;
                uint2 h02 = *(const uint2*)&Ah[oa];
                uint2 h13 = *(const uint2*)&Ah[oa + 64];
                uint2 l02 = *(const uint2*)&Al[oa];
                uint2 l13 = *(const uint2*)&Al[oa + 64];
#pragma unroll
                for (int j = 0; j < 4; j++) {
                    MMA_TF32(acc[i][j], h02.x, h13.x, h02.y, h13.y, bh[j][0], bh[j][1]);
                    MMA_TF32(acc[i][j], h02.x, h13.x, h02.y, h13.y, bl[j][0], bl[j][1]);
                    MMA_TF32(acc[i][j], l02.x, l13.x, l02.y, l13.y, bh[j][0], bh[j][1]);
                }
            }
        }
        __syncthreads();
        if (s + 1 < slabs) { storeA(); storeB(); __syncthreads(); }
    }

    // --- epilogue ---
#pragma unroll
    for (int i = 0; i < 4; i++) {
#pragma unroll
        for (int j = 0; j < 4; j++) {
            int r0 = m0 + wm + i * 16 + (lane >> 2);
            int n  = n0 + wn + j * 8 + (lane & 3) * 2;
            float b0 = 0.f, b1 = 0.f;
            if (bias) { b0 = bias[n]; b1 = bias[n + 1]; }
            if (r0 < M)
                *(float2*)(C + (long)r0 * N + n) =
                    make_float2(acc[i][j][0] + b0, acc[i][j][1] + b1);
            int r1 = r0 + 8;
            if (r1 < M)
                *(float2*)(C + (long)r1 * N + n) =
                    make_float2(acc[i][j][2] + b0, acc[i][j][3] + b1);
        }
    }
}

template<int AMODE, int BMODE>
__global__ void __launch_bounds__(256, 2)
gemm_kernel(const float* __restrict__ A, const float* __restrict__ Bm,
            float* __restrict__ C, int M, int N, int K,
            long sA, long sB, long sC, const float* __restrict__ bias) {
    A  += (long)blockIdx.z * sA;
    Bm += (long)blockIdx.z * sB;
    C  += (long)blockIdx.z * sC;
    gemm_core_tf32<AMODE, BMODE>(A, Bm, C, M, N, K, bias);
}

// 3 GEMMs sharing the same A, distinct B/C, selected by blockIdx.z.
struct Ptr3 { const float* b0; const float* b1; const float* b2;
              float* c0; float* c1; float* c2; };
__global__ void __launch_bounds__(256, 2)
gemm3_kernel(const float* __restrict__ A, Ptr3 p, int M, int N, int K) {
    const float* Bm = (blockIdx.z == 0) ? p.b0 : (blockIdx.z == 1) ? p.b1 : p.b2;
    float*       C  = (blockIdx.z == 0) ? p.c0 : (blockIdx.z == 1) ? p.c1 : p.c2;
    gemm_core_tf32<0, 0>(A, Bm, C, M, N, K, nullptr);
}

// 2 GEMMs sharing the same B (mem_keys, used transposed), distinct A/C.
struct PtrW { const float* a0; const float* a1; float* c0; float* c1; };
__global__ void __launch_bounds__(256, 2)
gemmW_kernel(PtrW p, const float* __restrict__ mk, int M, int N, int K) {
    const float* A = blockIdx.z ? p.a1 : p.a0;
    float*       C = blockIdx.z ? p.c1 : p.c0;
    gemm_core_tf32<0, 1>(A, mk, C, M, N, K, nullptr);
}

// ---------------- row softmax over 1024 cols ----------------
__global__ void __launch_bounds__(256) softmax1024(float* __restrict__ w) {
    __shared__ float sh[8];
    float* row = w + (long)blockIdx.x * M_;
    const int tid = threadIdx.x;
    float4 v = *(float4*)(row + tid * 4);
    float mx = fmaxf(fmaxf(v.x, v.y), fmaxf(v.z, v.w));
#pragma unroll
    for (int o = 16; o; o >>= 1) mx = fmaxf(mx, __shfl_xor_sync(~0u, mx, o));
    if ((tid & 31) == 0) sh[tid >> 5] = mx;
    __syncthreads();
    mx = sh[0];
#pragma unroll
    for (int i = 1; i < 8; i++) mx = fmaxf(mx, sh[i]);
    v.x = __expf(v.x - mx); v.y = __expf(v.y - mx);
    v.z = __expf(v.z - mx); v.w = __expf(v.w - mx);
    float s = v.x + v.y + v.z + v.w;
#pragma unroll
    for (int o = 16; o; o >>= 1) s += __shfl_xor_sync(~0u, s, o);
    __syncthreads();
    if ((tid & 31) == 0) sh[tid >> 5] = s;
    __syncthreads();
    s = sh[0] + sh[1] + sh[2] + sh[3] + sh[4] + sh[5] + sh[6] + sh[7];
    float inv = 1.f / s;
    v.x *= inv; v.y *= inv; v.z *= inv; v.w *= inv;
    *(float4*)(row + tid * 4) = v;
}

// ---------------- layernorm, row width 512, 128 threads ----------------
__global__ void __launch_bounds__(128)
layernorm512(const float* __restrict__ in, float* __restrict__ out,
             const float* __restrict__ gw, const float* __restrict__ bw) {
    __shared__ float sh[4];
    const int tid = threadIdx.x;
    const float* row = in + (long)blockIdx.x * D_;
    float4 v = *(const float4*)(row + tid * 4);
    float s = v.x + v.y + v.z + v.w;
#pragma unroll
    for (int o = 16; o; o >>= 1) s += __shfl_xor_sync(~0u, s, o);
    if ((tid & 31) == 0) sh[tid >> 5] = s;
    __syncthreads();
    float mu = (sh[0] + sh[1] + sh[2] + sh[3]) * (1.f / 512.f);
    float dx = v.x - mu, dy = v.y - mu, dz = v.z - mu, dw = v.w - mu;
    float sq = dx * dx + dy * dy + dz * dz + dw * dw;
#pragma unroll
    for (int o = 16; o; o >>= 1) sq += __shfl_xor_sync(~0u, sq, o);
    __syncthreads();
    if ((tid & 31) == 0) sh[tid >> 5] = sq;
    __syncthreads();
    float var = (sh[0] + sh[1] + sh[2] + sh[3]) * (1.f / 512.f);
    float inv = rsqrtf(var + EPS_);
    float4 g4 = *(const float4*)(gw + tid * 4);
    float4 b4 = *(const float4*)(bw + tid * 4);
    float4 o;
    o.x = dx * inv * g4.x + b4.x;
    o.y = dy * inv * g4.y + b4.y;
    o.z = dz * inv * g4.z + b4.z;
    o.w = dw * inv * g4.w + b4.w;
    *(float4*)(out + (long)blockIdx.x * D_ + tid * 4) = o;
}

// ---------------- banded flash attention ----------------
#define ATTN_SMEM_FLOATS (64 * 65 * 2 + 64 * 64 * 2)
__global__ void __launch_bounds__(256)
attn_kernel(const float* __restrict__ qh, const float* __restrict__ kh,
            const float* __restrict__ vh, float* __restrict__ out) {
    extern __shared__ float smem[];
    float (*Qs)[65] = (float (*)[65])smem;                 // 64x65
    float (*Ps)[65] = (float (*)[65])(smem + 64 * 65);     // 64x65
    float (*Ks)[64] = (float (*)[64])(smem + 64 * 65 * 2); // 64x64
    float (*Vs)[64] = (float (*)[64])(smem + 64 * 65 * 2 + 64 * 64);

    const int qt = blockIdx.x, h = blockIdx.y, b = blockIdx.z;
    const int q0 = qt * 64;
    const int tid = threadIdx.x;
    const int r = tid >> 2, cg = tid & 3;
    const long base = (long)b * S_ * D_ + h * HD_;

    for (int i = tid; i < 64 * 64; i += 256) {
        int rr = i >> 6, dd = i & 63;
        Qs[rr][dd] = (q0 + rr < S_) ? qh[base + (long)(q0 + rr) * D_ + dd] : 0.f;
    }

    float m = -1e30f, l = 0.f;
    float o[16];
#pragma unroll
    for (int i = 0; i < 16; i++) o[i] = 0.f;

    int klo = q0 - (WIN_ - 1); if (klo < 0) klo = 0;
    int khi = q0 + 63 + WIN_ - 1; if (khi > S_ - 1) khi = S_ - 1;

    for (int kt = klo >> 6; kt <= khi >> 6; ++kt) {
        const int k0 = kt << 6;
        __syncthreads();
        for (int i = tid; i < 64 * 64; i += 256) {
            int rr = i >> 6, dd = i & 63;
            bool ok = (k0 + rr < S_);
            long g = base + (long)(k0 + rr) * D_ + dd;
            Ks[rr][dd] = ok ? kh[g] : 0.f;
            Vs[rr][dd] = ok ? vh[g] : 0.f;
        }
        __syncthreads();

        float sreg[16];
#pragma unroll
        for (int j = 0; j < 16; j++) sreg[j] = 0.f;
#pragma unroll 8
        for (int d = 0; d < 64; d++) {
            float qd = Qs[r][d];
#pragma unroll
            for (int j = 0; j < 16; j++) sreg[j] += qd * Ks[cg * 16 + j][d];
        }

        const int qi = q0 + r;
        float tmax = -1e30f;
#pragma unroll
        for (int j = 0; j < 16; j++) {
            int kj = k0 + cg * 16 + j;
            int diff = qi - kj; if (diff < 0) diff = -diff;
            bool valid = (kj < S_) && (diff < WIN_);
            sreg[j] = valid ? sreg[j] * 0.125f : -1e30f;
            tmax = fmaxf(tmax, sreg[j]);
        }
        tmax = fmaxf(tmax, __shfl_xor_sync(0xffffffffu, tmax, 1));
        tmax = fmaxf(tmax, __shfl_xor_sync(0xffffffffu, tmax, 2));
        float mnew = fmaxf(m, tmax);
        float alpha = __expf(m - mnew);
        float lsum = 0.f;
#pragma unroll
        for (int j = 0; j < 16; j++) {
            // masked (sentinel) entries must contribute exactly 0, even when
            // mnew is itself the sentinel (fully-masked tile for this row).
            float p = (sreg[j] > -0.9e30f) ? __expf(sreg[j] - mnew) : 0.f;
            Ps[r][cg * 16 + j] = p;
            lsum += p;
        }
        lsum += __shfl_xor_sync(0xffffffffu, lsum, 1);
        lsum += __shfl_xor_sync(0xffffffffu, lsum, 2);
        l = l * alpha + lsum;
        m = mnew;
#pragma unroll
        for (int i = 0; i < 16; i++) o[i] *= alpha;
        __syncthreads();
#pragma unroll 4
        for (int j = 0; j < 64; j++) {
            float p = Ps[r][j];
#pragma unroll
            for (int i = 0; i < 16; i++) o[i] += p * Vs[j][cg * 16 + i];
        }
    }

    const int qi = q0 + r;
    if (qi < S_) {
        float inv = 1.f / l;
        float* orow = out + base + (long)qi * D_ + cg * 16;
#pragma unroll
        for (int i = 0; i < 16; i++) orow[i] = o[i] * inv;
    }
}

// ---------------- launch ----------------
extern "C" void kernel_launch(void* const* d_in, const int* in_sizes, int n_in,
                              void* d_out, int out_size) {
    const float* x        = (const float*)d_in[0];
    const float* pm       = (const float*)d_in[1];
    const float* mem_keys = (const float*)d_in[2];
    const float* mem_Wk   = (const float*)d_in[3];
    const float* mem_Wv   = (const float*)d_in[4];
    const float* mem_Wq   = (const float*)d_in[5];
    const float* attn_Wq  = (const float*)d_in[6];
    const float* attn_Wk  = (const float*)d_in[7];
    const float* attn_Wv  = (const float*)d_in[8];
    const float* attn_Wo  = (const float*)d_in[9];
    const float* ln1_g    = (const float*)d_in[10];
    const float* ln1_b    = (const float*)d_in[11];
    const float* ln2_g    = (const float*)d_in[12];
    const float* ln2_b    = (const float*)d_in[13];
    const float* out_W    = (const float*)d_in[14];
    const float* out_b    = (const float*)d_in[15];
    float* out = (float*)d_out;

    float *combined, *k, *v, *q, *w, *w2, *state, *memout, *h;
    float *qh, *kh, *vh, *aout, *ao2, *h2;
    cudaGetSymbolAddress((void**)&combined, g_combined);
    cudaGetSymbolAddress((void**)&k, g_k);
    cudaGetSymbolAddress((void**)&v, g_v);
    cudaGetSymbolAddress((void**)&q, g_q);
    cudaGetSymbolAddress((void**)&w, g_w);
    cudaGetSymbolAddress((void**)&w2, g_w2);
    cudaGetSymbolAddress((void**)&state, g_state);
    cudaGetSymbolAddress((void**)&memout, g_memout);
    cudaGetSymbolAddress((void**)&h, g_h);
    cudaGetSymbolAddress((void**)&qh, g_qh);
    cudaGetSymbolAddress((void**)&kh, g_kh);
    cudaGetSymbolAddress((void**)&vh, g_vh);
    cudaGetSymbolAddress((void**)&aout, g_aout);
    cudaGetSymbolAddress((void**)&ao2, g_ao2);
    cudaGetSymbolAddress((void**)&h2, g_h2);

    cudaFuncSetAttribute(attn_kernel,
                         cudaFuncAttributeMaxDynamicSharedMemorySize,
                         ATTN_SMEM_FLOATS * (int)sizeof(float));

    // 1. combined = [pm ; x]
    concat_kernel<<<(int)(((long)R_ * D_ + 255) / 256), 256>>>(x, pm, combined);

    const int MT = (R_ + 127) / 128;                // 33 row tiles

    // 2. memory k/v/q projections (batched, 396 CTAs)
    {
        Ptr3 p{mem_Wk, mem_Wv, mem_Wq, k, v, q};
        dim3 g(512 / 128, MT, 3);
        gemm3_kernel<<<g, 256>>>(combined, p, R_, D_, D_);
    }

    // 3. both gating GEMMs together: w_write = k@mkT, w_read = q@mkT
    {
        PtrW p{k, q, w, w2};
        dim3 g(1024 / 128, MT, 2);
        gemmW_kernel<<<g, 256>>>(p, mem_keys, R_, M_, D_);
    }
    softmax1024<<<R_, 256>>>(w);
    softmax1024<<<R_, 256>>>(w2);

    // 4. state[b] = w_write[b]^T @ v[b]   (M=1024, N=512, K=S)
    {
        dim3 gs(512 / 128, 1024 / 128, B_);
        gemm_kernel<1, 0><<<gs, 256>>>(w, v, state, M_, D_, S_,
                                       (long)S_ * M_, (long)S_ * D_, (long)M_ * D_, nullptr);
    }

    // 5. mem_out[b] = w_read[b] @ state[b]   (M=S, N=512, K=1024)
    {
        dim3 gm(512 / 128, (S_ + 127) / 128, B_);
        gemm_kernel<0, 0><<<gm, 256>>>(w2, state, memout, S_, D_, M_,
                                       (long)S_ * M_, (long)M_ * D_, (long)S_ * D_, nullptr);
    }

    // 6. LN1
    layernorm512<<<R_, 128>>>(memout, h, ln1_g, ln1_b);

    // 7. attention projections (batched)
    {
        Ptr3 p{attn_Wq, attn_Wk, attn_Wv, qh, kh, vh};
        dim3 g(512 / 128, MT, 3);
        gemm3_kernel<<<g, 256>>>(h, p, R_, D_, D_);
    }

    // 8. banded flash attention
    {
        dim3 ga((S_ + 63) / 64, H_, B_);
        attn_kernel<<<ga, 256, ATTN_SMEM_FLOATS * (int)sizeof(float)>>>(qh, kh, vh, aout);
    }

    // 9. output projection + LN2 + final linear (+bias)
    {
        dim3 g(512 / 128, MT, 1);
        gemm_kernel<0, 0><<<g, 256>>>(aout, attn_Wo, ao2, R_, D_, D_, 0, 0, 0, nullptr);
        layernorm512<<<R_, 128>>>(ao2, h2, ln2_g, ln2_b);
        gemm_kernel<0, 0><<<g, 256>>>(h2, out_W, out, R_, D_, D_, 0, 0, 0, out_b);
    }
}

// round 6
// speedup vs baseline: 1.7560x; 1.7560x over previous
#include <cuda_runtime.h>

// ---------------- problem constants ----------------
#define B_   2
#define L_   2048
#define D_   512
#define P_   32
#define M_   1024
#define H_   8
#define HD_  64
#define WIN_ 256
#define S_   (P_ + L_)     // 2080
#define R_   (B_ * S_)     // 4160
#define EPS_ 1e-5f

// ---------------- scratch (device globals, no allocation) ----------------
__device__ float g_combined[R_ * D_];
__device__ float g_k[R_ * D_];
__device__ float g_v[R_ * D_];
__device__ float g_q[R_ * D_];
__device__ float g_w[R_ * M_];          // w_write
__device__ float g_w2[R_ * M_];         // w_read
__device__ float g_state[B_ * M_ * D_];
__device__ float g_memout[R_ * D_];
__device__ float g_h[R_ * D_];
__device__ float g_qh[R_ * D_];
__device__ float g_kh[R_ * D_];
__device__ float g_vh[R_ * D_];
__device__ float g_aout[R_ * D_];
__device__ float g_ao2[R_ * D_];
__device__ float g_h2[R_ * D_];

// ---------------- concat: combined = [persistent ; x] ----------------
__global__ void concat_kernel(const float* __restrict__ x,
                              const float* __restrict__ pm,
                              float* __restrict__ c) {
    long i = (long)blockIdx.x * 256 + threadIdx.x;
    if (i >= (long)R_ * D_) return;
    int d = (int)(i % D_);
    long sd = i / D_;
    int s = (int)(sd % S_);
    int b = (int)(sd / S_);
    c[i] = (s < P_) ? pm[s * D_ + d]
                    : x[((long)b * L_ + (s - P_)) * D_ + d];
}

// ---------------- fp32 GEMM core: 64x128x16 tile, 256 threads ----------------
// (R3 core + double-buffered smem: ONE sync per K-slab)
// C[M x N] = A @ B (+ optional bias over N).
// AMODE=0: A row-major M x K.  AMODE=1: A stored K x M (use A^T, ld M).
// BMODE=0: B row-major K x N.  BMODE=1: B stored N x K (use B^T, ld K).
// Requirements: K % 16 == 0, N % 128 == 0; M guarded.
template<int AMODE, int BMODE>
__device__ __forceinline__ void gemm_core(
    const float* __restrict__ A, const float* __restrict__ Bm,
    float* __restrict__ C, int M, int N, int K, const float* __restrict__ bias) {
    __shared__ float As[2][16][64];    // 8 KB
    __shared__ float Bs[2][16][128];   // 16 KB
    const int tid = threadIdx.x;
    const int tx = tid & 15, ty = tid >> 4;
    const int m0 = blockIdx.y * 64, n0 = blockIdx.x * 128;

    float acc[4][8];
#pragma unroll
    for (int i = 0; i < 4; i++)
#pragma unroll
        for (int j = 0; j < 8; j++) acc[i][j] = 0.f;

    float4 ra, rb0, rb1;

    auto loadA = [&](int k0) {
        if (AMODE == 0) {
            int row = tid >> 2, kq = (tid & 3) << 2;
            ra = (m0 + row < M)
               ? *(const float4*)(A + (long)(m0 + row) * K + (k0 + kq))
               : make_float4(0.f, 0.f, 0.f, 0.f);
        } else {
            int k = tid >> 4, mq = (tid & 15) << 2;
            ra = (m0 + mq < M)
               ? *(const float4*)(A + (long)(k0 + k) * M + (m0 + mq))
               : make_float4(0.f, 0.f, 0.f, 0.f);
        }
    };
    auto loadB = [&](int k0) {
        if (BMODE == 0) {
            int k = tid >> 5, nq = (tid & 31) << 2;
            rb0 = *(const float4*)(Bm + (long)(k0 + k) * N + (n0 + nq));
            rb1 = *(const float4*)(Bm + (long)(k0 + k + 8) * N + (n0 + nq));
        } else {
            int col = tid >> 1, kq = (tid & 1) << 3;
            rb0 = *(const float4*)(Bm + (long)(n0 + col) * K + (k0 + kq));
            rb1 = *(const float4*)(Bm + (long)(n0 + col) * K + (k0 + kq + 4));
        }
    };
    auto storeA = [&](int bu) {
        if (AMODE == 0) {
            int row = tid >> 2, kq = (tid & 3) << 2;
            As[bu][kq + 0][row] = ra.x; As[bu][kq + 1][row] = ra.y;
            As[bu][kq + 2][row] = ra.z; As[bu][kq + 3][row] = ra.w;
        } else {
            int k = tid >> 4, mq = (tid & 15) << 2;
            *(float4*)&As[bu][k][mq] = ra;
        }
    };
    auto storeB = [&](int bu) {
        if (BMODE == 0) {
            int k = tid >> 5, nq = (tid & 31) << 2;
            *(float4*)&Bs[bu][k][nq]     = rb0;
            *(float4*)&Bs[bu][k + 8][nq] = rb1;
        } else {
            int col = tid >> 1, kq = (tid & 1) << 3;
            Bs[bu][kq + 0][col] = rb0.x; Bs[bu][kq + 1][col] = rb0.y;
            Bs[bu][kq + 2][col] = rb0.z; Bs[bu][kq + 3][col] = rb0.w;
            Bs[bu][kq + 4][col] = rb1.x; Bs[bu][kq + 5][col] = rb1.y;
            Bs[bu][kq + 6][col] = rb1.z; Bs[bu][kq + 7][col] = rb1.w;
        }
    };

    const int slabs = K / 16;
    loadA(0); loadB(0);
    storeA(0); storeB(0);
    __syncthreads();
    int buf = 0;

    for (int s = 0; s < slabs; s++) {
        if (s + 1 < slabs) { loadA((s + 1) * 16); loadB((s + 1) * 16); }
#pragma unroll
        for (int k = 0; k < 16; k++) {
            float a[4], b[8];
            *(float4*)a       = *(const float4*)&As[buf][k][ty * 4];
            *(float4*)b       = *(const float4*)&Bs[buf][k][tx * 4];
            *(float4*)(b + 4) = *(const float4*)&Bs[buf][k][64 + tx * 4];
#pragma unroll
            for (int i = 0; i < 4; i++)
#pragma unroll
                for (int j = 0; j < 8; j++) acc[i][j] += a[i] * b[j];
        }
        if (s + 1 < slabs) { storeA(buf ^ 1); storeB(buf ^ 1); }
        __syncthreads();
        buf ^= 1;
    }

    // --- epilogue ---
    float4 bia0 = make_float4(0.f, 0.f, 0.f, 0.f), bia1 = bia0;
    if (bias) {
        bia0 = *(const float4*)(bias + n0 + tx * 4);
        bia1 = *(const float4*)(bias + n0 + 64 + tx * 4);
    }
#pragma unroll
    for (int i = 0; i < 4; i++) {
        int m = m0 + ty * 4 + i;
        if (m < M) {
            float* crow = C + (long)m * N + n0;
            float4 o0 = make_float4(acc[i][0] + bia0.x, acc[i][1] + bia0.y,
                                    acc[i][2] + bia0.z, acc[i][3] + bia0.w);
            float4 o1 = make_float4(acc[i][4] + bia1.x, acc[i][5] + bia1.y,
                                    acc[i][6] + bia1.z, acc[i][7] + bia1.w);
            *(float4*)(crow + tx * 4)      = o0;
            *(float4*)(crow + 64 + tx * 4) = o1;
        }
    }
}

template<int AMODE, int BMODE>
__global__ void __launch_bounds__(256, 3)
gemm_kernel(const float* __restrict__ A, const float* __restrict__ Bm,
            float* __restrict__ C, int M, int N, int K,
            long sA, long sB, long sC, const float* __restrict__ bias) {
    A  += (long)blockIdx.z * sA;
    Bm += (long)blockIdx.z * sB;
    C  += (long)blockIdx.z * sC;
    gemm_core<AMODE, BMODE>(A, Bm, C, M, N, K, bias);
}

// 3 GEMMs sharing the same A, distinct B/C, selected by blockIdx.z.
struct Ptr3 { const float* b0; const float* b1; const float* b2;
              float* c0; float* c1; float* c2; };
__global__ void __launch_bounds__(256, 3)
gemm3_kernel(const float* __restrict__ A, Ptr3 p, int M, int N, int K) {
    const float* Bm = (blockIdx.z == 0) ? p.b0 : (blockIdx.z == 1) ? p.b1 : p.b2;
    float*       C  = (blockIdx.z == 0) ? p.c0 : (blockIdx.z == 1) ? p.c1 : p.c2;
    gemm_core<0, 0>(A, Bm, C, M, N, K, nullptr);
}

// 2 GEMMs sharing the same B (mem_keys, used transposed), distinct A/C.
struct PtrW { const float* a0; const float* a1; float* c0; float* c1; };
__global__ void __launch_bounds__(256, 3)
gemmW_kernel(PtrW p, const float* __restrict__ mk, int M, int N, int K) {
    const float* A = blockIdx.z ? p.a1 : p.a0;
    float*       C = blockIdx.z ? p.c1 : p.c0;
    gemm_core<0, 1>(A, mk, C, M, N, K, nullptr);
}

// ---------------- row softmax over 1024 cols ----------------
__global__ void __launch_bounds__(256) softmax1024(float* __restrict__ w) {
    __shared__ float sh[8];
    float* row = w + (long)blockIdx.x * M_;
    const int tid = threadIdx.x;
    float4 v = *(float4*)(row + tid * 4);
    float mx = fmaxf(fmaxf(v.x, v.y), fmaxf(v.z, v.w));
#pragma unroll
    for (int o = 16; o; o >>= 1) mx = fmaxf(mx, __shfl_xor_sync(~0u, mx, o));
    if ((tid & 31) == 0) sh[tid >> 5] = mx;
    __syncthreads();
    mx = sh[0];
#pragma unroll
    for (int i = 1; i < 8; i++) mx = fmaxf(mx, sh[i]);
    v.x = __expf(v.x - mx); v.y = __expf(v.y - mx);
    v.z = __expf(v.z - mx); v.w = __expf(v.w - mx);
    float s = v.x + v.y + v.z + v.w;
#pragma unroll
    for (int o = 16; o; o >>= 1) s += __shfl_xor_sync(~0u, s, o);
    __syncthreads();
    if ((tid & 31) == 0) sh[tid >> 5] = s;
    __syncthreads();
    s = sh[0] + sh[1] + sh[2] + sh[3] + sh[4] + sh[5] + sh[6] + sh[7];
    float inv = 1.f / s;
    v.x *= inv; v.y *= inv; v.z *= inv; v.w *= inv;
    *(float4*)(row + tid * 4) = v;
}

// ---------------- layernorm, row width 512, 128 threads ----------------
__global__ void __launch_bounds__(128)
layernorm512(const float* __restrict__ in, float* __restrict__ out,
             const float* __restrict__ gw, const float* __restrict__ bw) {
    __shared__ float sh[4];
    const int tid = threadIdx.x;
    const float* row = in + (long)blockIdx.x * D_;
    float4 v = *(const float4*)(row + tid * 4);
    float s = v.x + v.y + v.z + v.w;
#pragma unroll
    for (int o = 16; o; o >>= 1) s += __shfl_xor_sync(~0u, s, o);
    if ((tid & 31) == 0) sh[tid >> 5] = s;
    __syncthreads();
    float mu = (sh[0] + sh[1] + sh[2] + sh[3]) * (1.f / 512.f);
    float dx = v.x - mu, dy = v.y - mu, dz = v.z - mu, dw = v.w - mu;
    float sq = dx * dx + dy * dy + dz * dz + dw * dw;
#pragma unroll
    for (int o = 16; o; o >>= 1) sq += __shfl_xor_sync(~0u, sq, o);
    __syncthreads();
    if ((tid & 31) == 0) sh[tid >> 5] = sq;
    __syncthreads();
    float var = (sh[0] + sh[1] + sh[2] + sh[3]) * (1.f / 512.f);
    float inv = rsqrtf(var + EPS_);
    float4 g4 = *(const float4*)(gw + tid * 4);
    float4 b4 = *(const float4*)(bw + tid * 4);
    float4 o;
    o.x = dx * inv * g4.x + b4.x;
    o.y = dy * inv * g4.y + b4.y;
    o.z = dz * inv * g4.z + b4.z;
    o.w = dw * inv * g4.w + b4.w;
    *(float4*)(out + (long)blockIdx.x * D_ + tid * 4) = o;
}

// ---------------- banded flash attention (conflict-free smem) ----------------
// grid: (ceil(S/64), H, B), 256 threads. thread = (row r=tid>>2, colgroup cg=tid&3).
// Smem layouts (all float4-aligned, bank-conflict free for the access patterns):
//   Qs [64][68]                      banks 4r+d  (8 r-lanes distinct, cg broadcast)
//   Ks [64][64], col ^ 8*(row>>4)    the 4 cg row-groups hit 4 distinct bank quads
//   Vs [64][64], col ^ 8*(col>>5)    the 4 cg col-groups hit 4 distinct bank quads
//   Ps [64][69]                      scalar; loads conflict-free, stores 2-way
#define QS_STR 68
#define PS_STR 69
#define ATTN_SMEM_FLOATS (64 * QS_STR + 64 * PS_STR + 64 * 64 * 2)
__global__ void __launch_bounds__(256)
attn_kernel(const float* __restrict__ qh, const float* __restrict__ kh,
            const float* __restrict__ vh, float* __restrict__ out) {
    extern __shared__ float smem[];
    float* Qs = smem;                        // [64][68]
    float* Ps = smem + 64 * QS_STR;          // [64][69]
    float* Ks = Ps + 64 * PS_STR;            // [64][64] swizzled
    float* Vs = Ks + 64 * 64;                // [64][64] swizzled

    const int qt = blockIdx.x, h = blockIdx.y, b = blockIdx.z;
    const int q0 = qt * 64;
    const int tid = threadIdx.x;
    const int r = tid >> 2, cg = tid & 3;
    const int rowb = cg * 16;
    const long base = (long)b * S_ * D_ + h * HD_;

    // load Q tile (float4)
    for (int i = tid; i < 64 * 16; i += 256) {
        int rr = i >> 4, c4 = (i & 15) * 4;
        float4 qv = make_float4(0.f, 0.f, 0.f, 0.f);
        if (q0 + rr < S_)
            qv = *(const float4*)(qh + base + (long)(q0 + rr) * D_ + c4);
        *(float4*)&Qs[rr * QS_STR + c4] = qv;
    }

    float m = -1e30f, l = 0.f;
    float o[16];
#pragma unroll
    for (int i = 0; i < 16; i++) o[i] = 0.f;

    int klo = q0 - (WIN_ - 1); if (klo < 0) klo = 0;
    int khi = q0 + 63 + WIN_ - 1; if (khi > S_ - 1) khi = S_ - 1;

    for (int kt = klo >> 6; kt <= khi >> 6; ++kt) {
        const int k0 = kt << 6;
        __syncthreads();   // protect Ks/Vs/Ps from previous iteration
        for (int i = tid; i < 64 * 16; i += 256) {
            int rr = i >> 4, c4 = (i & 15) * 4;
            float4 kv = make_float4(0.f, 0.f, 0.f, 0.f), vv = kv;
            if (k0 + rr < S_) {
                long g = base + (long)(k0 + rr) * D_ + c4;
                kv = *(const float4*)(kh + g);
                vv = *(const float4*)(vh + g);
            }
            *(float4*)&Ks[rr * 64 + (c4 ^ ((rr >> 4) * 8))] = kv;
            *(float4*)&Vs[rr * 64 + (c4 ^ ((c4 >> 5) * 8))] = vv;
        }
        __syncthreads();

        // QK: 16 keys per thread (rows cg*16..+15), all 64 d.
        float sreg[16];
#pragma unroll
        for (int j = 0; j < 16; j++) sreg[j] = 0.f;
        const int kx = cg * 8;
#pragma unroll 4
        for (int d0 = 0; d0 < 64; d0 += 4) {
            float4 q4 = *(const float4*)&Qs[r * QS_STR + d0];
            const int kc = d0 ^ kx;
#pragma unroll
            for (int j = 0; j < 16; j++) {
                float4 k4 = *(const float4*)&Ks[(rowb + j) * 64 + kc];
                sreg[j] += q4.x * k4.x + q4.y * k4.y + q4.z * k4.z + q4.w * k4.w;
            }
        }

        const int qi = q0 + r;
        float tmax = -1e30f;
#pragma unroll
        for (int j = 0; j < 16; j++) {
            int kj = k0 + rowb + j;
            int diff = qi - kj; if (diff < 0) diff = -diff;
            bool valid = (kj < S_) && (diff < WIN_);
            sreg[j] = valid ? sreg[j] * 0.125f : -1e30f;
            tmax = fmaxf(tmax, sreg[j]);
        }
        tmax = fmaxf(tmax, __shfl_xor_sync(0xffffffffu, tmax, 1));
        tmax = fmaxf(tmax, __shfl_xor_sync(0xffffffffu, tmax, 2));
        float mnew = fmaxf(m, tmax);
        float alpha = __expf(m - mnew);
        float lsum = 0.f;
#pragma unroll
        for (int j = 0; j < 16; j++) {
            // masked (sentinel) entries must contribute exactly 0, even when
            // mnew is itself the sentinel (fully-masked tile for this row).
            float p = (sreg[j] > -0.9e30f) ? __expf(sreg[j] - mnew) : 0.f;
            Ps[r * PS_STR + rowb + j] = p;
            lsum += p;
        }
        lsum += __shfl_xor_sync(0xffffffffu, lsum, 1);
        lsum += __shfl_xor_sync(0xffffffffu, lsum, 2);
        l = l * alpha + lsum;
        m = mnew;
#pragma unroll
        for (int i = 0; i < 16; i++) o[i] *= alpha;
        __syncthreads();   // Ps visible to all 4 lanes of each row

        // PV: o[0..15] over cols cg*16..+15, all 64 keys.
        const int vx = (cg >> 1) * 8;
#pragma unroll 4
        for (int j = 0; j < 64; j++) {
            float p = Ps[r * PS_STR + j];
#pragma unroll
            for (int i4 = 0; i4 < 4; i4++) {
                float4 v4 = *(const float4*)&Vs[j * 64 + ((rowb + i4 * 4) ^ vx)];
                o[i4 * 4 + 0] += p * v4.x;
                o[i4 * 4 + 1] += p * v4.y;
                o[i4 * 4 + 2] += p * v4.z;
                o[i4 * 4 + 3] += p * v4.w;
            }
        }
    }

    const int qi = q0 + r;
    if (qi < S_) {
        float inv = 1.f / l;
        float* orow = out + base + (long)qi * D_ + rowb;
#pragma unroll
        for (int i = 0; i < 16; i++) orow[i] = o[i] * inv;
    }
}

// ---------------- launch ----------------
extern "C" void kernel_launch(void* const* d_in, const int* in_sizes, int n_in,
                              void* d_out, int out_size) {
    const float* x        = (const float*)d_in[0];
    const float* pm       = (const float*)d_in[1];
    const float* mem_keys = (const float*)d_in[2];
    const float* mem_Wk   = (const float*)d_in[3];
    const float* mem_Wv   = (const float*)d_in[4];
    const float* mem_Wq   = (const float*)d_in[5];
    const float* attn_Wq  = (const float*)d_in[6];
    const float* attn_Wk  = (const float*)d_in[7];
    const float* attn_Wv  = (const float*)d_in[8];
    const float* attn_Wo  = (const float*)d_in[9];
    const float* ln1_g    = (const float*)d_in[10];
    const float* ln1_b    = (const float*)d_in[11];
    const float* ln2_g    = (const float*)d_in[12];
    const float* ln2_b    = (const float*)d_in[13];
    const float* out_W    = (const float*)d_in[14];
    const float* out_b    = (const float*)d_in[15];
    float* out = (float*)d_out;

    float *combined, *k, *v, *q, *w, *w2, *state, *memout, *h;
    float *qh, *kh, *vh, *aout, *ao2, *h2;
    cudaGetSymbolAddress((void**)&combined, g_combined);
    cudaGetSymbolAddress((void**)&k, g_k);
    cudaGetSymbolAddress((void**)&v, g_v);
    cudaGetSymbolAddress((void**)&q, g_q);
    cudaGetSymbolAddress((void**)&w, g_w);
    cudaGetSymbolAddress((void**)&w2, g_w2);
    cudaGetSymbolAddress((void**)&state, g_state);
    cudaGetSymbolAddress((void**)&memout, g_memout);
    cudaGetSymbolAddress((void**)&h, g_h);
    cudaGetSymbolAddress((void**)&qh, g_qh);
    cudaGetSymbolAddress((void**)&kh, g_kh);
    cudaGetSymbolAddress((void**)&vh, g_vh);
    cudaGetSymbolAddress((void**)&aout, g_aout);
    cudaGetSymbolAddress((void**)&ao2, g_ao2);
    cudaGetSymbolAddress((void**)&h2, g_h2);

    cudaFuncSetAttribute(attn_kernel,
                         cudaFuncAttributeMaxDynamicSharedMemorySize,
                         ATTN_SMEM_FLOATS * (int)sizeof(float));

    // 1. combined = [pm ; x]
    concat_kernel<<<(int)(((long)R_ * D_ + 255) / 256), 256>>>(x, pm, combined);

    const int MT = (R_ + 63) / 64;                 // 65 row tiles

    // 2. memory k/v/q projections (batched, 780 CTAs)
    {
        Ptr3 p{mem_Wk, mem_Wv, mem_Wq, k, v, q};
        dim3 g(512 / 128, MT, 3);
        gemm3_kernel<<<g, 256>>>(combined, p, R_, D_, D_);
    }

    // 3. both gating GEMMs: w_write = k@mkT, w_read = q@mkT (1040 CTAs)
    {
        PtrW p{k, q, w, w2};
        dim3 g(1024 / 128, MT, 2);
        gemmW_kernel<<<g, 256>>>(p, mem_keys, R_, M_, D_);
    }
    softmax1024<<<R_, 256>>>(w);
    softmax1024<<<R_, 256>>>(w2);

    // 4. state[b] = w_write[b]^T @ v[b]   (M=1024, N=512, K=S)
    {
        dim3 gs(512 / 128, 1024 / 64, B_);
        gemm_kernel<1, 0><<<gs, 256>>>(w, v, state, M_, D_, S_,
                                       (long)S_ * M_, (long)S_ * D_, (long)M_ * D_, nullptr);
    }

    // 5. mem_out[b] = w_read[b] @ state[b]   (M=S, N=512, K=1024)
    {
        dim3 gm(512 / 128, (S_ + 63) / 64, B_);
        gemm_kernel<0, 0><<<gm, 256>>>(w2, state, memout, S_, D_, M_,
                                       (long)S_ * M_, (long)M_ * D_, (long)S_ * D_, nullptr);
    }

    // 6. LN1
    layernorm512<<<R_, 128>>>(memout, h, ln1_g, ln1_b);

    // 7. attention projections (batched)
    {
        Ptr3 p{attn_Wq, attn_Wk, attn_Wv, qh, kh, vh};
        dim3 g(512 / 128, MT, 3);
        gemm3_kernel<<<g, 256>>>(h, p, R_, D_, D_);
    }

    // 8. banded flash attention
    {
        dim3 ga((S_ + 63) / 64, H_, B_);
        attn_kernel<<<ga, 256, ATTN_SMEM_FLOATS * (int)sizeof(float)>>>(qh, kh, vh, aout);
    }

    // 9. output projection + LN2 + final linear (+bias)
    {
        dim3 g(512 / 128, MT, 1);
        gemm_kernel<0, 0><<<g, 256>>>(aout, attn_Wo, ao2, R_, D_, D_, 0, 0, 0, nullptr);
        layernorm512<<<R_, 128>>>(ao2, h2, ln2_g, ln2_b);
        gemm_kernel<0, 0><<<g, 256>>>(h2, out_W, out, R_, D_, D_, 0, 0, 0, out_b);
    }
}

// round 8
// speedup vs baseline: 2.7189x; 1.5484x over previous
#include <cuda_runtime.h>
#include <cuda_bf16.h>

// ---------------- problem constants ----------------
#define B_   2
#define L_   2048
#define D_   512
#define P_   32
#define M_   1024
#define H_   8
#define HD_  64
#define WIN_ 256
#define S_   (P_ + L_)     // 2080
#define R_   (B_ * S_)     // 4160
#define EPS_ 1e-5f

// ---------------- scratch (device globals, no allocation) ----------------
__device__ float g_combined[R_ * D_];
__device__ float g_k[R_ * D_];
__device__ float g_v[R_ * D_];
__device__ float g_q[R_ * D_];
__device__ float g_w[R_ * M_];          // w_write
__device__ float g_w2[R_ * M_];         // w_read
__device__ float g_state[B_ * M_ * D_];
__device__ float g_memout[R_ * D_];
__device__ float g_h[R_ * D_];
__device__ float g_qh[R_ * D_];
__device__ float g_kh[R_ * D_];
__device__ float g_vh[R_ * D_];
__device__ float g_aout[R_ * D_];
__device__ float g_ao2[R_ * D_];
__device__ float g_h2[R_ * D_];

// ---------------- bf16 m16n8k16 MMA (available on plain sm_103 target) ---
#define MMA_BF16(d, a0, a1, a2, a3, b0, b1) \
    asm("mma.sync.aligned.m16n8k16.row.col.f32.bf16.bf16.f32 " \
        "{%0,%1,%2,%3}, {%4,%5,%6,%7}, {%8,%9}, {%0,%1,%2,%3};" \
        : "+f"((d)[0]), "+f"((d)[1]), "+f"((d)[2]), "+f"((d)[3]) \
        : "r"(a0), "r"(a1), "r"(a2), "r"(a3), "r"(b0), "r"(b1))

// hi/lo bf16 split of a float pair; packed words have LOW half = first elem.
__device__ __forceinline__ void hilo2(float x, float y, unsigned& h, unsigned& l) {
    __nv_bfloat162 hb = __floats2bfloat162_rn(x, y);
    float2 hf = __bfloat1622float2(hb);
    __nv_bfloat162 lb = __floats2bfloat162_rn(x - hf.x, y - hf.y);
    h = reinterpret_cast<unsigned&>(hb);
    l = reinterpret_cast<unsigned&>(lb);
}

// smem tile layout: [16 kpairs][136 cols] uints per matrix-half.
// word [kp][c] = {X[c][2kp], X[c][2kp+1]} (bf16x2, low = even k).
// Fragment LDS banks: (136*kp + c) mod 32 = (8*kp + c) mod 32 -> the
// (kp = lane%4 (+4), c = base + lane/4) pattern covers 32 distinct banks.
#define KPS  16          // kpairs per slab (K-slab = 32)
#define TSTR 136         // padded col stride (words)
#define MHALF (KPS * TSTR)                  // 2176 words per matrix-half
#define BUFW  (4 * MHALF)                   // Ahi|Alo|Bhi|Blo per buffer
#define BF_SMEM_BYTES (2 * BUFW * 4)        // 69632 B, double buffered

// stage a row-major [rows, ld] source slab (32 k) into hi/lo tiles
__device__ __forceinline__ void stage_rm(
    const float* __restrict__ src, int r0, int RM, int ld, int k0,
    unsigned* __restrict__ Hi, unsigned* __restrict__ Lo, int tid) {
    const int row = tid >> 1;                 // 0..127 (tile col index)
    const int kh  = (tid & 1) << 4;           // 0 or 16
    const float* p = src + (long)(r0 + row) * ld + k0 + kh;
    const bool ok = (r0 + row) < RM;
#pragma unroll
    for (int j = 0; j < 4; j++) {
        float4 a = ok ? *(const float4*)(p + j * 4)
                      : make_float4(0.f, 0.f, 0.f, 0.f);
        int kp = (kh >> 1) + 2 * j;
        unsigned h0, h1, l0, l1;
        hilo2(a.x, a.y, h0, l0);
        hilo2(a.z, a.w, h1, l1);
        Hi[kp * TSTR + row] = h0; Hi[(kp + 1) * TSTR + row] = h1;
        Lo[kp * TSTR + row] = l0; Lo[(kp + 1) * TSTR + row] = l1;
    }
}

// stage a [K, ld] source slab TRANSPOSED (tile cols = source columns)
__device__ __forceinline__ void stage_tr(
    const float* __restrict__ src, int c0, int CM, int ld, int k0,
    unsigned* __restrict__ Hi, unsigned* __restrict__ Lo, int tid) {
    const int kp = tid >> 4;                  // 0..15
    const int cq = (tid & 15) << 3;           // 0..120 step 8
    const bool ok = (c0 + cq) < CM;
    const float* p0 = src + (long)(k0 + 2 * kp) * ld + c0 + cq;
    const float* p1 = p0 + ld;
    float4 x0 = make_float4(0.f, 0.f, 0.f, 0.f), x1 = x0, y0 = x0, y1 = x0;
    if (ok) {
        x0 = *(const float4*)(p0);     x1 = *(const float4*)(p0 + 4);
        y0 = *(const float4*)(p1);     y1 = *(const float4*)(p1 + 4);
    }
    unsigned h[8], l[8];
    hilo2(x0.x, y0.x, h[0], l[0]); hilo2(x0.y, y0.y, h[1], l[1]);
    hilo2(x0.z, y0.z, h[2], l[2]); hilo2(x0.w, y0.w, h[3], l[3]);
    hilo2(x1.x, y1.x, h[4], l[4]); hilo2(x1.y, y1.y, h[5], l[5]);
    hilo2(x1.z, y1.z, h[6], l[6]); hilo2(x1.w, y1.w, h[7], l[7]);
    *(uint4*)&Hi[kp * TSTR + cq]     = make_uint4(h[0], h[1], h[2], h[3]);
    *(uint4*)&Hi[kp * TSTR + cq + 4] = make_uint4(h[4], h[5], h[6], h[7]);
    *(uint4*)&Lo[kp * TSTR + cq]     = make_uint4(l[0], l[1], l[2], l[3]);
    *(uint4*)&Lo[kp * TSTR + cq + 4] = make_uint4(l[4], l[5], l[6], l[7]);
}

// ---------------- bf16 2-split GEMM core: 128x128 tile, K-slab 32 --------
// C = A @ B (+bias).  ATR=0: A [M,K] row-major.  ATR=1: A stored [K,M].
// BTR=0: B stored [K,N].  BTR=1: B stored [N,K].
// Warp tile 64x32 (2x4 warp grid): 4 m-frags x 4 n-frags.
template<int ATR, int BTR>
__device__ __forceinline__ void bf_core(
    const float* __restrict__ A, const float* __restrict__ Bm,
    float* __restrict__ C, int M, int N, int K, const float* __restrict__ bias) {
    extern __shared__ unsigned smg[];
    const int tid = threadIdx.x, lane = tid & 31, wid = tid >> 5;
    const int wm = (wid >> 2) * 64, wn = (wid & 3) * 32;
    const int m0 = blockIdx.y * 128, n0 = blockIdx.x * 128;

    float acc[4][4][4];
#pragma unroll
    for (int i = 0; i < 4; i++)
#pragma unroll
        for (int j = 0; j < 4; j++)
#pragma unroll
            for (int c = 0; c < 4; c++) acc[i][j][c] = 0.f;

    auto stage = [&](int s, int b) {
        const int k0 = s * 32;
        unsigned* AH = smg + b * BUFW;
        unsigned* AL = AH + MHALF;
        unsigned* BH = AH + 2 * MHALF;
        unsigned* BL = AH + 3 * MHALF;
        if (ATR == 0) stage_rm(A, m0, M, K, k0, AH, AL, tid);
        else          stage_tr(A, m0, M, M, k0, AH, AL, tid);
        if (BTR == 0) stage_tr(Bm, n0, N, N, k0, BH, BL, tid);
        else          stage_rm(Bm, n0, N, K, k0, BH, BL, tid);
    };

    const int slabs = K >> 5;
    stage(0, 0);
    __syncthreads();

    for (int s = 0; s < slabs; s++) {
        const int buf = s & 1;
        const unsigned* AH = smg + buf * BUFW;
        const unsigned* AL = AH + MHALF;
        const unsigned* BH = AH + 2 * MHALF;
        const unsigned* BL = AH + 3 * MHALF;
#pragma unroll
        for (int t = 0; t < 2; t++) {
            const int kb = (t * 8 + (lane & 3)) * TSTR;
            const int k4 = kb + 4 * TSTR;
            const int rsel = lane >> 2;
            unsigned bh0[4], bh1[4], bl0[4], bl1[4];
#pragma unroll
            for (int j = 0; j < 4; j++) {
                int c = wn + j * 8 + rsel;
                bh0[j] = BH[kb + c]; bh1[j] = BH[k4 + c];
                bl0[j] = BL[kb + c]; bl1[j] = BL[k4 + c];
            }
#pragma unroll
            for (int i = 0; i < 4; i++) {
                int c = wm + i * 16 + rsel;
                unsigned h0 = AH[kb + c], h1 = AH[kb + c + 8];
                unsigned h2 = AH[k4 + c], h3 = AH[k4 + c + 8];
                unsigned l0 = AL[kb + c], l1 = AL[kb + c + 8];
                unsigned l2 = AL[k4 + c], l3 = AL[k4 + c + 8];
#pragma unroll
                for (int j = 0; j < 4; j++) {
                    MMA_BF16(acc[i][j], h0, h1, h2, h3, bh0[j], bh1[j]);
                    MMA_BF16(acc[i][j], h0, h1, h2, h3, bl0[j], bl1[j]);
                    MMA_BF16(acc[i][j], l0, l1, l2, l3, bh0[j], bh1[j]);
                }
            }
        }
        if (s + 1 < slabs) stage(s + 1, buf ^ 1);
        __syncthreads();
    }

    // --- epilogue: c0,c1 -> row lane/4, cols 2*(lane%4); c2,c3 -> row+8 ---
    const int er = lane >> 2, ec = (lane & 3) * 2;
#pragma unroll
    for (int i = 0; i < 4; i++) {
#pragma unroll
        for (int j = 0; j < 4; j++) {
            int cc = n0 + wn + j * 8 + ec;
            float b0 = 0.f, b1 = 0.f;
            if (bias) { b0 = bias[cc]; b1 = bias[cc + 1]; }
            int r0w = m0 + wm + i * 16 + er;
            if (r0w < M)
                *(float2*)(C + (long)r0w * N + cc) =
                    make_float2(acc[i][j][0] + b0, acc[i][j][1] + b1);
            int r1w = r0w + 8;
            if (r1w < M)
                *(float2*)(C + (long)r1w * N + cc) =
                    make_float2(acc[i][j][2] + b0, acc[i][j][3] + b1);
        }
    }
}

template<int ATR, int BTR>
__global__ void __launch_bounds__(256, 2)
bf_gemm(const float* __restrict__ A, const float* __restrict__ Bm,
        float* __restrict__ C, int M, int N, int K,
        long sA, long sB, long sC, const float* __restrict__ bias) {
    bf_core<ATR, BTR>(A + blockIdx.z * sA, Bm + blockIdx.z * sB,
                      C + blockIdx.z * sC, M, N, K, bias);
}

struct Ptr3 { const float* b0; const float* b1; const float* b2;
              float* c0; float* c1; float* c2; };
__global__ void __launch_bounds__(256, 2)
bf_gemm3(const float* __restrict__ A, Ptr3 p, int M, int N, int K) {
    const float* Bm = (blockIdx.z == 0) ? p.b0 : (blockIdx.z == 1) ? p.b1 : p.b2;
    float*       C  = (blockIdx.z == 0) ? p.c0 : (blockIdx.z == 1) ? p.c1 : p.c2;
    bf_core<0, 0>(A, Bm, C, M, N, K, nullptr);
}

struct PtrW { const float* a0; const float* a1; float* c0; float* c1; };
__global__ void __launch_bounds__(256, 2)
bf_gemmW(PtrW p, const float* __restrict__ mk, int M, int N, int K) {
    bf_core<0, 1>(blockIdx.z ? p.a1 : p.a0, mk,
                  blockIdx.z ? p.c1 : p.c0, M, N, K, nullptr);
}

// ---------------- concat: combined = [persistent ; x] ----------------
__global__ void concat_kernel(const float* __restrict__ x,
                              const float* __restrict__ pm,
                              float* __restrict__ c) {
    long i = (long)blockIdx.x * 256 + threadIdx.x;
    if (i >= (long)R_ * D_) return;
    int d = (int)(i % D_);
    long sd = i / D_;
    int s = (int)(sd % S_);
    int b = (int)(sd / S_);
    c[i] = (s < P_) ? pm[s * D_ + d]
                    : x[((long)b * L_ + (s - P_)) * D_ + d];
}

// ---------------- row softmax over 1024 cols ----------------
__global__ void __launch_bounds__(256) softmax1024(float* __restrict__ w) {
    __shared__ float sh[8];
    float* row = w + (long)blockIdx.x * M_;
    const int tid = threadIdx.x;
    float4 v = *(float4*)(row + tid * 4);
    float mx = fmaxf(fmaxf(v.x, v.y), fmaxf(v.z, v.w));
#pragma unroll
    for (int o = 16; o; o >>= 1) mx = fmaxf(mx, __shfl_xor_sync(~0u, mx, o));
    if ((tid & 31) == 0) sh[tid >> 5] = mx;
    __syncthreads();
    mx = sh[0];
#pragma unroll
    for (int i = 1; i < 8; i++) mx = fmaxf(mx, sh[i]);
    v.x = __expf(v.x - mx); v.y = __expf(v.y - mx);
    v.z = __expf(v.z - mx); v.w = __expf(v.w - mx);
    float s = v.x + v.y + v.z + v.w;
#pragma unroll
    for (int o = 16; o; o >>= 1) s += __shfl_xor_sync(~0u, s, o);
    __syncthreads();
    if ((tid & 31) == 0) sh[tid >> 5] = s;
    __syncthreads();
    s = sh[0] + sh[1] + sh[2] + sh[3] + sh[4] + sh[5] + sh[6] + sh[7];
    float inv = 1.f / s;
    v.x *= inv; v.y *= inv; v.z *= inv; v.w *= inv;
    *(float4*)(row + tid * 4) = v;
}

// ---------------- layernorm, row width 512, 128 threads ----------------
__global__ void __launch_bounds__(128)
layernorm512(const float* __restrict__ in, float* __restrict__ out,
             const float* __restrict__ gw, const float* __restrict__ bw) {
    __shared__ float sh[4];
    const int tid = threadIdx.x;
    const float* row = in + (long)blockIdx.x * D_;
    float4 v = *(const float4*)(row + tid * 4);
    float s = v.x + v.y + v.z + v.w;
#pragma unroll
    for (int o = 16; o; o >>= 1) s += __shfl_xor_sync(~0u, s, o);
    if ((tid & 31) == 0) sh[tid >> 5] = s;
    __syncthreads();
    float mu = (sh[0] + sh[1] + sh[2] + sh[3]) * (1.f / 512.f);
    float dx = v.x - mu, dy = v.y - mu, dz = v.z - mu, dw = v.w - mu;
    float sq = dx * dx + dy * dy + dz * dz + dw * dw;
#pragma unroll
    for (int o = 16; o; o >>= 1) sq += __shfl_xor_sync(~0u, sq, o);
    __syncthreads();
    if ((tid & 31) == 0) sh[tid >> 5] = sq;
    __syncthreads();
    float var = (sh[0] + sh[1] + sh[2] + sh[3]) * (1.f / 512.f);
    float inv = rsqrtf(var + EPS_);
    float4 g4 = *(const float4*)(gw + tid * 4);
    float4 b4 = *(const float4*)(bw + tid * 4);
    float4 o;
    o.x = dx * inv * g4.x + b4.x;
    o.y = dy * inv * g4.y + b4.y;
    o.z = dz * inv * g4.z + b4.z;
    o.w = dw * inv * g4.w + b4.w;
    *(float4*)(out + (long)blockIdx.x * D_ + tid * 4) = o;
}

// ---------------- banded flash attention (R6, conflict-free smem) ---------
#define QS_STR 68
#define PS_STR 69
#define ATTN_SMEM_FLOATS (64 * QS_STR + 64 * PS_STR + 64 * 64 * 2)
__global__ void __launch_bounds__(256)
attn_kernel(const float* __restrict__ qh, const float* __restrict__ kh,
            const float* __restrict__ vh, float* __restrict__ out) {
    extern __shared__ float smema[];
    float* Qs = smema;
    float* Ps = smema + 64 * QS_STR;
    float* Ks = Ps + 64 * PS_STR;
    float* Vs = Ks + 64 * 64;

    const int qt = blockIdx.x, h = blockIdx.y, b = blockIdx.z;
    const int q0 = qt * 64;
    const int tid = threadIdx.x;
    const int r = tid >> 2, cg = tid & 3;
    const int rowb = cg * 16;
    const long base = (long)b * S_ * D_ + h * HD_;

    for (int i = tid; i < 64 * 16; i += 256) {
        int rr = i >> 4, c4 = (i & 15) * 4;
        float4 qv = make_float4(0.f, 0.f, 0.f, 0.f);
        if (q0 + rr < S_)
            qv = *(const float4*)(qh + base + (long)(q0 + rr) * D_ + c4);
        *(float4*)&Qs[rr * QS_STR + c4] = qv;
    }

    float m = -1e30f, l = 0.f;
    float o[16];
#pragma unroll
    for (int i = 0; i < 16; i++) o[i] = 0.f;

    int klo = q0 - (WIN_ - 1); if (klo < 0) klo = 0;
    int khi = q0 + 63 + WIN_ - 1; if (khi > S_ - 1) khi = S_ - 1;

    for (int kt = klo >> 6; kt <= khi >> 6; ++kt) {
        const int k0 = kt << 6;
        __syncthreads();
        for (int i = tid; i < 64 * 16; i += 256) {
            int rr = i >> 4, c4 = (i & 15) * 4;
            float4 kv = make_float4(0.f, 0.f, 0.f, 0.f), vv = kv;
            if (k0 + rr < S_) {
                long g = base + (long)(k0 + rr) * D_ + c4;
                kv = *(const float4*)(kh + g);
                vv = *(const float4*)(vh + g);
            }
            *(float4*)&Ks[rr * 64 + (c4 ^ ((rr >> 4) * 8))] = kv;
            *(float4*)&Vs[rr * 64 + (c4 ^ ((c4 >> 5) * 8))] = vv;
        }
        __syncthreads();

        float sreg[16];
#pragma unroll
        for (int j = 0; j < 16; j++) sreg[j] = 0.f;
        const int kx = cg * 8;
#pragma unroll 4
        for (int d0 = 0; d0 < 64; d0 += 4) {
            float4 q4 = *(const float4*)&Qs[r * QS_STR + d0];
            const int kc = d0 ^ kx;
#pragma unroll
            for (int j = 0; j < 16; j++) {
                float4 k4 = *(const float4*)&Ks[(rowb + j) * 64 + kc];
                sreg[j] += q4.x * k4.x + q4.y * k4.y + q4.z * k4.z + q4.w * k4.w;
            }
        }

        const int qi = q0 + r;
        float tmax = -1e30f;
#pragma unroll
        for (int j = 0; j < 16; j++) {
            int kj = k0 + rowb + j;
            int diff = qi - kj; if (diff < 0) diff = -diff;
            bool valid = (kj < S_) && (diff < WIN_);
            sreg[j] = valid ? sreg[j] * 0.125f : -1e30f;
            tmax = fmaxf(tmax, sreg[j]);
        }
        tmax = fmaxf(tmax, __shfl_xor_sync(0xffffffffu, tmax, 1));
        tmax = fmaxf(tmax, __shfl_xor_sync(0xffffffffu, tmax, 2));
        float mnew = fmaxf(m, tmax);
        float alpha = __expf(m - mnew);
        float lsum = 0.f;
#pragma unroll
        for (int j = 0; j < 16; j++) {
            float p = (sreg[j] > -0.9e30f) ? __expf(sreg[j] - mnew) : 0.f;
            Ps[r * PS_STR + rowb + j] = p;
            lsum += p;
        }
        lsum += __shfl_xor_sync(0xffffffffu, lsum, 1);
        lsum += __shfl_xor_sync(0xffffffffu, lsum, 2);
        l = l * alpha + lsum;
        m = mnew;
#pragma unroll
        for (int i = 0; i < 16; i++) o[i] *= alpha;
        __syncthreads();

        const int vx = (cg >> 1) * 8;
#pragma unroll 4
        for (int j = 0; j < 64; j++) {
            float p = Ps[r * PS_STR + j];
#pragma unroll
            for (int i4 = 0; i4 < 4; i4++) {
                float4 v4 = *(const float4*)&Vs[j * 64 + ((rowb + i4 * 4) ^ vx)];
                o[i4 * 4 + 0] += p * v4.x;
                o[i4 * 4 + 1] += p * v4.y;
                o[i4 * 4 + 2] += p * v4.z;
                o[i4 * 4 + 3] += p * v4.w;
            }
        }
    }

    const int qi = q0 + r;
    if (qi < S_) {
        float inv = 1.f / l;
        float* orow = out + base + (long)qi * D_ + rowb;
#pragma unroll
        for (int i = 0; i < 16; i++) orow[i] = o[i] * inv;
    }
}

// ---------------- launch ----------------
extern "C" void kernel_launch(void* const* d_in, const int* in_sizes, int n_in,
                              void* d_out, int out_size) {
    const float* x        = (const float*)d_in[0];
    const float* pm       = (const float*)d_in[1];
    const float* mem_keys = (const float*)d_in[2];
    const float* mem_Wk   = (const float*)d_in[3];
    const float* mem_Wv   = (const float*)d_in[4];
    const float* mem_Wq   = (const float*)d_in[5];
    const float* attn_Wq  = (const float*)d_in[6];
    const float* attn_Wk  = (const float*)d_in[7];
    const float* attn_Wv  = (const float*)d_in[8];
    const float* attn_Wo  = (const float*)d_in[9];
    const float* ln1_g    = (const float*)d_in[10];
    const float* ln1_b    = (const float*)d_in[11];
    const float* ln2_g    = (const float*)d_in[12];
    const float* ln2_b    = (const float*)d_in[13];
    const float* out_W    = (const float*)d_in[14];
    const float* out_b    = (const float*)d_in[15];
    float* out = (float*)d_out;

    float *combined, *k, *v, *q, *w, *w2, *state, *memout, *h;
    float *qh, *kh, *vh, *aout, *ao2, *h2;
    cudaGetSymbolAddress((void**)&combined, g_combined);
    cudaGetSymbolAddress((void**)&k, g_k);
    cudaGetSymbolAddress((void**)&v, g_v);
    cudaGetSymbolAddress((void**)&q, g_q);
    cudaGetSymbolAddress((void**)&w, g_w);
    cudaGetSymbolAddress((void**)&w2, g_w2);
    cudaGetSymbolAddress((void**)&state, g_state);
    cudaGetSymbolAddress((void**)&memout, g_memout);
    cudaGetSymbolAddress((void**)&h, g_h);
    cudaGetSymbolAddress((void**)&qh, g_qh);
    cudaGetSymbolAddress((void**)&kh, g_kh);
    cudaGetSymbolAddress((void**)&vh, g_vh);
    cudaGetSymbolAddress((void**)&aout, g_aout);
    cudaGetSymbolAddress((void**)&ao2, g_ao2);
    cudaGetSymbolAddress((void**)&h2, g_h2);

    cudaFuncSetAttribute(attn_kernel,
                         cudaFuncAttributeMaxDynamicSharedMemorySize,
                         ATTN_SMEM_FLOATS * (int)sizeof(float));
    cudaFuncSetAttribute(bf_gemm<0, 0>,
                         cudaFuncAttributeMaxDynamicSharedMemorySize, BF_SMEM_BYTES);
    cudaFuncSetAttribute(bf_gemm<1, 0>,
                         cudaFuncAttributeMaxDynamicSharedMemorySize, BF_SMEM_BYTES);
    cudaFuncSetAttribute(bf_gemm3,
                         cudaFuncAttributeMaxDynamicSharedMemorySize, BF_SMEM_BYTES);
    cudaFuncSetAttribute(bf_gemmW,
                         cudaFuncAttributeMaxDynamicSharedMemorySize, BF_SMEM_BYTES);

    // 1. combined = [pm ; x]
    concat_kernel<<<(int)(((long)R_ * D_ + 255) / 256), 256>>>(x, pm, combined);

    const int MT = (R_ + 127) / 128;   // 33

    // 2. memory k/v/q projections
    {
        Ptr3 p{mem_Wk, mem_Wv, mem_Wq, k, v, q};
        bf_gemm3<<<dim3(4, MT, 3), 256, BF_SMEM_BYTES>>>(combined, p, R_, D_, D_);
    }

    // 3. gating: w_write = k@mkT, w_read = q@mkT  (mem_keys stored [N,K])
    {
        PtrW p{k, q, w, w2};
        bf_gemmW<<<dim3(8, MT, 2), 256, BF_SMEM_BYTES>>>(p, mem_keys, R_, M_, D_);
    }
    softmax1024<<<R_, 256>>>(w);
    softmax1024<<<R_, 256>>>(w2);

    // 4. state[b] = w_write[b]^T @ v[b]   (A stored [K=S, M=1024])
    bf_gemm<1, 0><<<dim3(4, 8, B_), 256, BF_SMEM_BYTES>>>(
        w, v, state, M_, D_, S_,
        (long)S_ * M_, (long)S_ * D_, (long)M_ * D_, nullptr);

    // 5. mem_out[b] = w_read[b] @ state[b]
    bf_gemm<0, 0><<<dim3(4, (S_ + 127) / 128, B_), 256, BF_SMEM_BYTES>>>(
        w2, state, memout, S_, D_, M_,
        (long)S_ * M_, (long)M_ * D_, (long)S_ * D_, nullptr);

    // 6. LN1
    layernorm512<<<R_, 128>>>(memout, h, ln1_g, ln1_b);

    // 7. attention projections
    {
        Ptr3 p{attn_Wq, attn_Wk, attn_Wv, qh, kh, vh};
        bf_gemm3<<<dim3(4, MT, 3), 256, BF_SMEM_BYTES>>>(h, p, R_, D_, D_);
    }

    // 8. banded flash attention
    attn_kernel<<<dim3((S_ + 63) / 64, H_, B_), 256,
                  ATTN_SMEM_FLOATS * (int)sizeof(float)>>>(qh, kh, vh, aout);

    // 9. output projection + LN2 + final linear (+bias)
    bf_gemm<0, 0><<<dim3(4, MT, 1), 256, BF_SMEM_BYTES>>>(
        aout, attn_Wo, ao2, R_, D_, D_, 0, 0, 0, nullptr);
    layernorm512<<<R_, 128>>>(ao2, h2, ln2_g, ln2_b);
    bf_gemm<0, 0><<<dim3(4, MT, 1), 256, BF_SMEM_BYTES>>>(
        h2, out_W, out, R_, D_, D_, 0, 0, 0, out_b);
}